// round 5
// baseline (speedup 1.0000x reference)
#include <cuda_runtime.h>

// Problem constants
#define T_STEPS 256
#define BATCH   128
#define HID     1024
#define LAT     128
#define PIECE   128

#define NBLK 128            // one CTA per 8 hidden units; co-resident on 148 SMs
#define NTHR 256            // 8 warps -> 2 per SMSP
#define KC    64            // k-chunk of h streamed through smem
#define NCHUNK (HID / KC)   // 16
#define K4S    (KC / 4)     // 16 k4-groups per chunk

typedef unsigned long long ull;

// Persistent state (device globals: no allocation inside kernel_launch)
__device__ float    g_h[2][BATCH * HID];  // h double buffer, layout [b][k]
__device__ unsigned g_bar;                // monotonic grid-barrier counter

// ---------------- helpers ----------------
__device__ __forceinline__ void cp_async16(void* sdst, const void* gsrc) {
    unsigned s = (unsigned)__cvta_generic_to_shared(sdst);
    asm volatile("cp.async.cg.shared.global [%0], [%1], 16;\n" :: "r"(s), "l"(gsrc));
}
__device__ __forceinline__ void cp_commit() { asm volatile("cp.async.commit_group;\n"); }
__device__ __forceinline__ void cp_wait0()  { asm volatile("cp.async.wait_group 0;\n"); }

__device__ __forceinline__ void unpack2(ull v, float& lo, float& hi) {
    asm("mov.b64 {%0, %1}, %2;" : "=f"(lo), "=f"(hi) : "l"(v));
}
// packed fp32 pair FMA: d.lo += a.lo*b.lo ; d.hi += a.hi*b.hi
__device__ __forceinline__ void ffma2(ull& d, ull a, ull b) {
    asm("fma.rn.f32x2 %0, %1, %2, %0;" : "+l"(d) : "l"(a), "l"(b));
}
__device__ __forceinline__ float sigf(float x) { return 1.0f / (1.0f + __expf(-x)); }

// Grid barrier: 128 CTAs co-resident (1 CTA/SM). Every thread fences its own
// stores before arrival. Monotonic counter => valid across graph replays.
__device__ __forceinline__ void grid_bar() {
    __threadfence();
    __syncthreads();
    if (threadIdx.x == 0) {
        unsigned my = atomicAdd(&g_bar, 1u);
        unsigned target = my - (my % NBLK) + NBLK;
        while (*(volatile unsigned*)&g_bar < target) { __nanosleep(40); }
        __threadfence();
    }
    __syncthreads();
}

// ---------------- persistent kernel ----------------
// CTA blk owns hidden units u = blk*8..blk*8+7 (all 4 gates) for all batch rows,
// plus FC output column p = blk.
// Thread: tx = tid&7 (unit u=tx), tyb = tid>>3 in 0..31 -> batch rows tyb*4..tyb*4+3.
// Gate column inside CTA: col = u*4 + gate (0=i,1=f,2=g,3=o).
// FFMA2 vector lanes carry (k even, k odd) partial sums; summed at epilogue.
extern "C" __global__ void __launch_bounds__(NTHR, 1)
lstm_persistent_kernel(const float* __restrict__ z,
                       const float* __restrict__ w_ih,
                       const float* __restrict__ w_hh,
                       const float* __restrict__ b_ih,
                       const float* __restrict__ b_hh,
                       const float* __restrict__ W_fc,
                       const float* __restrict__ b_fc,
                       float* __restrict__ out)
{
    extern __shared__ float smem[];
    float* Wsm  = smem;                 // [HID/4][32][4] w_hh slice, interleaved (128 KB)
    float* Hst  = Wsm + HID * 32;       // 2 x [KC/4][BATCH][4] h chunk bufs     (64 KB)
    float* wfcs = Hst + 2 * KC * BATCH; // [HID] W_fc row blk                    (4 KB)
    float* bsum = wfcs + HID;           // [32] b_ih + b_hh slice
    float* yred = bsum + 32;            // [256] FC half-sum exchange
    float* Xg   = Hst;                  // [32][BATCH] step-0 gates (aliases Hst)

    const int tid = threadIdx.x;
    const int blk = blockIdx.x;
    const int tx  = tid & 7;            // unit
    const int tyb = tid >> 3;           // batch group (4 rows)

    // ---------- prologue ----------
    // W slice: Wsm[(k>>2)*128 + col*4 + (k&3)] = w_hh[row(col)][k]
    for (int col = 0; col < 32; ++col) {
        int u = col >> 2, g = col & 3;
        int row = g * HID + blk * 8 + u;
        const float* src = w_hh + (size_t)row * HID;
        for (int k = tid; k < HID; k += NTHR)
            Wsm[(k >> 2) * 128 + col * 4 + (k & 3)] = src[k];
    }
    if (tid < 32) {
        int u = tid >> 2, g = tid & 3;
        bsum[tid] = b_ih[g * HID + blk * 8 + u] + b_hh[g * HID + blk * 8 + u];
    }
    for (int k = tid; k < HID; k += NTHR) wfcs[k] = W_fc[(size_t)blk * HID + k];
    const float bfc = b_fc[blk];

    // Step-0 input gates: Xg[col][b] = z[b,:] . w_ih[row(col),:]
    for (int g = 0; g < 4; ++g) {
        int col = tx * 4 + g;
        const float* wi = w_ih + (size_t)(g * HID + blk * 8 + tx) * LAT;
        for (int pb = 0; pb < 4; ++pb) {
            int b = tyb * 4 + pb;
            const float* zb = z + (size_t)b * LAT;
            float s = 0.f;
            #pragma unroll 4
            for (int l = 0; l < LAT; ++l) s += zb[l] * wi[l];
            Xg[col * BATCH + b] = s;
        }
    }
    __syncthreads();

    float cst[4];
    #pragma unroll
    for (int i = 0; i < 4; ++i) cst[i] = 0.f;

    // t in [0,T]: t>=1 streams h_{t-1} (GEMM for step t + FC for y_{t-1});
    // t<T runs the gate epilogue producing h_t; t==T is the final FC pass.
    for (int t = 0; t <= T_STEPS; ++t) {
        ull acc[4][4];   // [batch i][gate j], lanes = (k even, k odd)
        ull yacc = 0;

        if (t >= 1) {
            #pragma unroll
            for (int i = 0; i < 4; ++i)
                #pragma unroll
                for (int j = 0; j < 4; ++j) acc[i][j] = 0;

            const float* hsrc = g_h[t & 1];   // h_{t-1}, [b][k]

            // prefetch chunk 0: 2048 x 16B, smem interleaved [k4][b][4]
            {
                float* dst = Hst;
                #pragma unroll
                for (int r = 0; r < 8; ++r) {
                    int m = tid + NTHR * r;      // m = k4*128 + b
                    int k4 = m >> 7, b = m & 127;
                    cp_async16(dst + (size_t)m * 4,
                               hsrc + (size_t)b * HID + k4 * 4);
                }
                cp_commit();
            }

            const int khalf = tid >> 7;       // FC k-half
            const int brow  = tid & 127;      // FC batch row

            for (int ck = 0; ck < NCHUNK; ++ck) {
                cp_wait0();
                __syncthreads();              // chunk ck visible; buf (ck+1)&1 free

                if (ck + 1 < NCHUNK) {
                    float* dst = Hst + ((ck + 1) & 1) * (KC * BATCH);
                    const float* srcb = hsrc + (ck + 1) * KC;
                    #pragma unroll
                    for (int r = 0; r < 8; ++r) {
                        int m = tid + NTHR * r;
                        int k4 = m >> 7, b = m & 127;
                        cp_async16(dst + (size_t)m * 4,
                                   srcb + (size_t)b * HID + k4 * 4);
                    }
                    cp_commit();
                }

                const float* hb = Hst + (ck & 1) * (KC * BATCH);
                const float* wb = Wsm + ck * (K4S * 128);

                // GEMM: 16 k4-groups x (8 LDS.128 + 32 FFMA2)
                #pragma unroll 4
                for (int k4 = 0; k4 < K4S; ++k4) {
                    ull h2[4][2], w2[4][2];
                    #pragma unroll
                    for (int i = 0; i < 4; ++i) {
                        ulonglong2 v = *(const ulonglong2*)
                            (hb + k4 * 512 + (tyb * 4 + i) * 4);
                        h2[i][0] = v.x; h2[i][1] = v.y;
                    }
                    #pragma unroll
                    for (int j = 0; j < 4; ++j) {
                        ulonglong2 v = *(const ulonglong2*)
                            (wb + k4 * 128 + (tx * 4 + j) * 4);
                        w2[j][0] = v.x; w2[j][1] = v.y;
                    }
                    #pragma unroll
                    for (int i = 0; i < 4; ++i)
                        #pragma unroll
                        for (int j = 0; j < 4; ++j) {
                            ffma2(acc[i][j], h2[i][0], w2[j][0]);
                            ffma2(acc[i][j], h2[i][1], w2[j][1]);
                        }
                }

                // FC partial for y_{t-1}: this thread's half of the chunk
                {
                    const float* hfc = hb + khalf * 8 * 512 + brow * 4;
                    const float* wfc = wfcs + ck * KC + khalf * 32;
                    #pragma unroll
                    for (int q = 0; q < 8; ++q) {
                        ulonglong2 hv = *(const ulonglong2*)(hfc + q * 512);
                        ulonglong2 wv = *(const ulonglong2*)(wfc + q * 4);
                        ffma2(yacc, hv.x, wv.x);
                        ffma2(yacc, hv.y, wv.y);
                    }
                }
            }

            // combine FC halves, write y_{t-1}[b][blk]
            {
                float ylo, yhi; unpack2(yacc, ylo, yhi);
                yred[tid] = ylo + yhi;
            }
            __syncthreads();
            if (tid < 128)
                out[(size_t)tid * (T_STEPS * PIECE) + (size_t)(t - 1) * PIECE + blk]
                    = yred[tid] + yred[tid + 128] + bfc;
        }

        if (t < T_STEPS) {
            // gate epilogue -> h_t, c_t for unit tx, batch rows tyb*4..+3
            float hv[4];
            #pragma unroll
            for (int i = 0; i < 4; ++i) {
                float gv[4];
                #pragma unroll
                for (int j = 0; j < 4; ++j) {
                    float base = bsum[tx * 4 + j];
                    if (t == 0) {
                        gv[j] = Xg[(tx * 4 + j) * BATCH + tyb * 4 + i] + base;
                    } else {
                        float lo, hi; unpack2(acc[i][j], lo, hi);
                        gv[j] = lo + hi + base;
                    }
                }
                float i_ = sigf(gv[0]), f_ = sigf(gv[1]);
                float g_ = tanhf(gv[2]), o_ = sigf(gv[3]);
                float c = f_ * cst[i] + i_ * g_;
                cst[i] = c;
                hv[i] = o_ * tanhf(c);
            }
            // write h_t: g_h[(t+1)&1][b][blk*8+tx]
            float* hd = g_h[(t + 1) & 1];
            #pragma unroll
            for (int i = 0; i < 4; ++i)
                hd[(size_t)(tyb * 4 + i) * HID + blk * 8 + tx] = hv[i];

            grid_bar();   // h_t visible to all CTAs before step t+1
        }
    }
}

// ---------------- launch ----------------
extern "C" void kernel_launch(void* const* d_in, const int* in_sizes, int n_in,
                              void* d_out, int out_size)
{
    // metadata order: current_batch_size, z, w_ih, w_hh, b_ih, b_hh, W_fc, b_fc
    int off = (n_in >= 8) ? 1 : 0;
    const float* z    = (const float*)d_in[off + 0];
    const float* w_ih = (const float*)d_in[off + 1];
    const float* w_hh = (const float*)d_in[off + 2];
    const float* b_ih = (const float*)d_in[off + 3];
    const float* b_hh = (const float*)d_in[off + 4];
    const float* W_fc = (const float*)d_in[off + 5];
    const float* b_fc = (const float*)d_in[off + 6];

    const int smem_bytes = (HID * 32 + 2 * KC * BATCH + HID + 32 + NTHR)
                           * (int)sizeof(float);
    cudaFuncSetAttribute(lstm_persistent_kernel,
                         cudaFuncAttributeMaxDynamicSharedMemorySize, smem_bytes);

    lstm_persistent_kernel<<<NBLK, NTHR, smem_bytes>>>(
        z, w_ih, w_hh, b_ih, b_hh, W_fc, b_fc, (float*)d_out);
}

// round 6
// speedup vs baseline: 3.1057x; 3.1057x over previous
#include <cuda_runtime.h>

// Problem constants
#define T_STEPS 256
#define BATCH   128
#define HID     1024
#define LAT     128
#define PIECE   128

#define NBLK 128            // one CTA per 8 hidden units; co-resident on 148 SMs
#define NTHR 256            // 8 warps (2/SMSP), two 128-thread k-halves
#define KC   32             // k-chunk of h streamed through smem
#define NCHUNK   32
#define NCH_HALF 16         // chunks per k-half

typedef unsigned long long ull;

// Persistent state (device globals: no allocation inside kernel_launch)
__device__ float    g_h[2][HID * BATCH];  // h double buffer, layout [k][b]
__device__ unsigned g_bar;                // monotonic grid-barrier counter

// ---------------- helpers ----------------
__device__ __forceinline__ void cp_async16(void* sdst, const void* gsrc) {
    unsigned s = (unsigned)__cvta_generic_to_shared(sdst);
    asm volatile("cp.async.cg.shared.global [%0], [%1], 16;\n" :: "r"(s), "l"(gsrc));
}
__device__ __forceinline__ void cp_commit() { asm volatile("cp.async.commit_group;\n"); }
__device__ __forceinline__ void cp_wait0()  { asm volatile("cp.async.wait_group 0;\n"); }

__device__ __forceinline__ ull pack2(float lo, float hi) {
    ull r; asm("mov.b64 %0, {%1, %2};" : "=l"(r) : "f"(lo), "f"(hi)); return r;
}
__device__ __forceinline__ void unpack2(ull v, float& lo, float& hi) {
    asm("mov.b64 {%0, %1}, %2;" : "=f"(lo), "=f"(hi) : "l"(v));
}
// packed fp32 pair FMA: d.lo += a.lo*b.lo ; d.hi += a.hi*b.hi
__device__ __forceinline__ void ffma2(ull& d, ull a, ull b) {
    asm("fma.rn.f32x2 %0, %1, %2, %0;" : "+l"(d) : "l"(a), "l"(b));
}
__device__ __forceinline__ float sigf(float x) { return 1.0f / (1.0f + __expf(-x)); }

// Named barrier over one 128-thread k-half (IDs 1,2; 0 is __syncthreads)
__device__ __forceinline__ void bar_half(int kh) {
    asm volatile("bar.sync %0, 128;" :: "r"(1 + kh) : "memory");
}

// Grid barrier: 128 CTAs co-resident (1 CTA/SM). Every thread fences its own
// stores before arrival. Monotonic counter => valid across graph replays.
__device__ __forceinline__ void grid_bar() {
    __threadfence();
    __syncthreads();
    if (threadIdx.x == 0) {
        unsigned my = atomicAdd(&g_bar, 1u);
        unsigned target = my - (my % NBLK) + NBLK;
        while (*(volatile unsigned*)&g_bar < target) { __nanosleep(40); }
        __threadfence();
    }
    __syncthreads();
}

// ---------------- persistent kernel ----------------
// CTA blk owns hidden units u = blk*8..blk*8+7 (4 gates each) for all batch rows,
// plus FC output column p = blk.
// Thread: kh = tid>>7 (k-half), th = tid&127, tx = th&7 (unit), ty = th>>3 (0..15).
// GEMM: each thread accumulates 8 batch rows (ty*8..+7) x 4 gate cols over its
// k-half; halves exchange partial sums through smem once per step.
// Gate column inside CTA: col = u*4 + gate (0=i,1=f,2=g,3=o).
extern "C" __global__ void __launch_bounds__(NTHR, 1)
lstm_persistent_kernel(const float* __restrict__ z,
                       const float* __restrict__ w_ih,
                       const float* __restrict__ w_hh,
                       const float* __restrict__ b_ih,
                       const float* __restrict__ b_hh,
                       const float* __restrict__ W_fc,
                       const float* __restrict__ b_fc,
                       float* __restrict__ out)
{
    extern __shared__ float smem[];
    float* Wsm    = smem;                   // [HID][32] w_hh slice, k-major (128 KB)
    float* Hst    = Wsm + HID * 32;         // 4 bufs of KC*BATCH: (kh,buf)   (64 KB)
    float* wfcs   = Hst + 4 * KC * BATCH;   // [HID] W_fc row blk             (4 KB)
    float* bsum   = wfcs + HID;             // [32] b_ih + b_hh slice
    float* fcpart = bsum + 32;              // [2][128] FC partials
    float* exchf  = fcpart + 256;           // exchange buf (16 KB), aliases Xg
    ull*   exch   = (ull*)exchf;            // [8][2][128] donated acc ulls
    float* Xg     = exchf;                  // [32][BATCH] step-0 gates (alias)

    const int tid = threadIdx.x;
    const int blk = blockIdx.x;
    const int kh  = tid >> 7;     // k-half
    const int th  = tid & 127;    // local id within half
    const int tx  = th & 7;       // unit
    const int ty  = th >> 3;      // batch group (8 rows)

    // ---------- prologue: persistent data ----------
    for (int col = 0; col < 32; ++col) {
        int u = col >> 2, g = col & 3;
        const float* src = w_hh + (size_t)(g * HID + blk * 8 + u) * HID;
        for (int k = tid; k < HID; k += NTHR)
            Wsm[k * 32 + col] = src[k];
    }
    if (tid < 32) {
        int u = tid >> 2, g = tid & 3;
        bsum[tid] = b_ih[g * HID + blk * 8 + u] + b_hh[g * HID + blk * 8 + u];
    }
    for (int k = tid; k < HID; k += NTHR) wfcs[k] = W_fc[(size_t)blk * HID + k];
    const float bfc = b_fc[blk];

    // Step-0 input gates: Xg[col][b] = z[b,:] . w_ih[row(col),:]
    // Thread covers its kept rows: b = ty*8 + kh*4 + 0..3
    for (int g = 0; g < 4; ++g) {
        int col = tx * 4 + g;
        const float* wi = w_ih + (size_t)(g * HID + blk * 8 + tx) * LAT;
        for (int pb = 0; pb < 4; ++pb) {
            int b = ty * 8 + kh * 4 + pb;
            const float* zb = z + (size_t)b * LAT;
            float s = 0.f;
            #pragma unroll 4
            for (int l = 0; l < LAT; ++l) s += zb[l] * wi[l];
            Xg[col * BATCH + b] = s;
        }
    }
    __syncthreads();

    // c state: 4 kept rows (kh=0 -> rows ty*8+0..3 ; kh=1 -> rows ty*8+4..7)
    float cst[4];
    #pragma unroll
    for (int i = 0; i < 4; ++i) cst[i] = 0.f;

    const int kbase = kh * 2;        // kept batch-pairs p = kbase, kbase+1
    const int dbase = 2 - kbase;     // donated pairs

    // t in [0,T]: t>=1 streams h_{t-1} (GEMM step t + FC y_{t-1});
    // t<T runs the gate epilogue producing h_t; t==T is the final FC pass.
    for (int t = 0; t <= T_STEPS; ++t) {
        ull  acc[4][4];   // [batch pair p][gate j], lanes = (row 2p, 2p+1)
        float yacc = 0.f;

        if (t >= 1) {
            #pragma unroll
            for (int p = 0; p < 4; ++p)
                #pragma unroll
                for (int j = 0; j < 4; ++j) acc[p][j] = 0;

            const float* hsrc = g_h[t & 1];       // h_{t-1}, [k][b]
            const int cb = kh * NCH_HALF;         // this half's first chunk

            // prefetch chunk 0 of this half (fully coalesced 16B float4s)
            {
                float* dst = Hst + (kh * 2) * (KC * BATCH);
                const float* src = hsrc + (size_t)cb * KC * BATCH;
                #pragma unroll
                for (int r = 0; r < 8; ++r)
                    cp_async16(dst + (size_t)(th + 128 * r) * 4,
                               src + (size_t)(th + 128 * r) * 4);
                cp_commit();
            }

            for (int ck = 0; ck < NCH_HALF; ++ck) {
                cp_wait0();
                bar_half(kh);               // chunk ck visible to whole half

                if (ck + 1 < NCH_HALF) {
                    float* dst = Hst + (kh * 2 + ((ck + 1) & 1)) * (KC * BATCH);
                    const float* src = hsrc + (size_t)(cb + ck + 1) * KC * BATCH;
                    #pragma unroll
                    for (int r = 0; r < 8; ++r)
                        cp_async16(dst + (size_t)(th + 128 * r) * 4,
                                   src + (size_t)(th + 128 * r) * 4);
                    cp_commit();
                }

                const float* hb = Hst + (kh * 2 + (ck & 1)) * (KC * BATCH);
                const float* wb = Wsm + (size_t)(cb + ck) * KC * 32;

                // GEMM: per k: 3x LDS.128 + 4 pack MOV + 16 FFMA2
                #pragma unroll 4
                for (int k = 0; k < KC; ++k) {
                    float4 w4 = *(const float4*)(wb + k * 32 + tx * 4);
                    ull w2[4] = { pack2(w4.x, w4.x), pack2(w4.y, w4.y),
                                  pack2(w4.z, w4.z), pack2(w4.w, w4.w) };
                    ulonglong2 ha = *(const ulonglong2*)(hb + k * BATCH + ty * 8);
                    ulonglong2 hc = *(const ulonglong2*)(hb + k * BATCH + ty * 8 + 4);
                    ull h2[4] = { ha.x, ha.y, hc.x, hc.y };
                    #pragma unroll
                    for (int p = 0; p < 4; ++p)
                        #pragma unroll
                        for (int j = 0; j < 4; ++j)
                            ffma2(acc[p][j], h2[p], w2[j]);
                }

                // FC partial for y_{t-1}: this thread handles batch row b = th
                {
                    const float* wf = wfcs + (cb + ck) * KC;
                    float yp = 0.f;
                    #pragma unroll 8
                    for (int k = 0; k < KC; ++k)
                        yp += hb[k * BATCH + th] * wf[k];
                    yacc += yp;
                }
            }

            fcpart[kh * 128 + th] = yacc;

            // donate the batch-pairs the other half will finish
            #pragma unroll
            for (int pi = 0; pi < 2; ++pi)
                #pragma unroll
                for (int j = 0; j < 4; ++j)
                    exch[(pi * 4 + j) * 256 + kh * 128 + th] = acc[dbase + pi][j];
        }

        __syncthreads();   // fcpart + exch visible CTA-wide

        if (t >= 1 && tid < 128)
            out[(size_t)tid * (T_STEPS * PIECE) + (size_t)(t - 1) * PIECE + blk]
                = fcpart[tid] + fcpart[128 + tid] + bfc;

        if (t < T_STEPS) {
            // gate epilogue for kept rows b = ty*8 + kh*4 + 0..3, unit tx
            float hv[4];
            #pragma unroll
            for (int pi = 0; pi < 2; ++pi) {
                int p = kbase + pi;
                float glo[4], ghi[4];
                #pragma unroll
                for (int j = 0; j < 4; ++j) {
                    float base = bsum[tx * 4 + j];
                    if (t == 0) {
                        glo[j] = Xg[(tx * 4 + j) * BATCH + ty * 8 + 2 * p]     + base;
                        ghi[j] = Xg[(tx * 4 + j) * BATCH + ty * 8 + 2 * p + 1] + base;
                    } else {
                        float al, ah, bl, bh;
                        unpack2(acc[p][j], al, ah);
                        unpack2(exch[(pi * 4 + j) * 256 + (1 - kh) * 128 + th], bl, bh);
                        glo[j] = al + bl + base;
                        ghi[j] = ah + bh + base;
                    }
                }
                {
                    float i_ = sigf(glo[0]), f_ = sigf(glo[1]);
                    float g_ = tanhf(glo[2]), o_ = sigf(glo[3]);
                    float c = f_ * cst[pi * 2] + i_ * g_;
                    cst[pi * 2] = c;
                    hv[pi * 2] = o_ * tanhf(c);
                }
                {
                    float i_ = sigf(ghi[0]), f_ = sigf(ghi[1]);
                    float g_ = tanhf(ghi[2]), o_ = sigf(ghi[3]);
                    float c = f_ * cst[pi * 2 + 1] + i_ * g_;
                    cst[pi * 2 + 1] = c;
                    hv[pi * 2 + 1] = o_ * tanhf(c);
                }
            }
            // write h_t: row j = blk*8+tx, batch b = ty*8 + kh*4 .. +3 (float4)
            float* hd = g_h[(t + 1) & 1]
                      + (size_t)(blk * 8 + tx) * BATCH + ty * 8 + kh * 4;
            *(float4*)hd = make_float4(hv[0], hv[1], hv[2], hv[3]);

            grid_bar();   // h_t visible to all CTAs before step t+1
        }
    }
}

// ---------------- launch ----------------
extern "C" void kernel_launch(void* const* d_in, const int* in_sizes, int n_in,
                              void* d_out, int out_size)
{
    // metadata order: current_batch_size, z, w_ih, w_hh, b_ih, b_hh, W_fc, b_fc
    int off = (n_in >= 8) ? 1 : 0;
    const float* z    = (const float*)d_in[off + 0];
    const float* w_ih = (const float*)d_in[off + 1];
    const float* w_hh = (const float*)d_in[off + 2];
    const float* b_ih = (const float*)d_in[off + 3];
    const float* b_hh = (const float*)d_in[off + 4];
    const float* W_fc = (const float*)d_in[off + 5];
    const float* b_fc = (const float*)d_in[off + 6];

    const int smem_bytes = (HID * 32 + 4 * KC * BATCH + HID + 32 + 256 + 4096)
                           * (int)sizeof(float);
    cudaFuncSetAttribute(lstm_persistent_kernel,
                         cudaFuncAttributeMaxDynamicSharedMemorySize, smem_bytes);

    lstm_persistent_kernel<<<NBLK, NTHR, smem_bytes>>>(
        z, w_ih, w_hh, b_ih, b_hh, W_fc, b_fc, (float*)d_out);
}